// round 16
// baseline (speedup 1.0000x reference)
#include <cuda_runtime.h>

#define BB 2
#define CC 64
#define HH 96
#define WW 192
#define DD 48
#define GG 8
#define HW (HH*WW)
#define NCH 4

// ---------------- scratch (static device globals; no allocation) ----------------
__device__ float g_fln[BB*GG*HW*8];              // [b][g][h][w][c]
__device__ float g_frn[BB*GG*HW*8];              // [b][g][h][w][c]
__device__ float g_base[(size_t)BB*DD*GG*HW];    // [b][d][g][h][w]
__device__ float g_sw2[3*BB*HW];                 // [s][b][hw]
__device__ float g_wpack2[5184];                 // [s][kd][kh][gi][kw][g] (un-dup)
__device__ float g_w1pack[65*9*32];              // [ic][tap][oc]
__device__ float g_pmid[(size_t)NCH*BB*32*HW];   // partial conv32 outputs
__device__ float g_bnscale[32];
__device__ float g_bnbias[32];

// ---------------- f32x2 helpers ----------------
typedef unsigned long long ull;
__device__ __forceinline__ ull pk2(float lo, float hi) {
    ull r;
    asm("mov.b64 %0, {%1, %2};" : "=l"(r) : "f"(lo), "f"(hi));
    return r;
}
__device__ __forceinline__ void upk2(float& lo, float& hi, ull v) {
    asm("mov.b64 {%0, %1}, %2;" : "=f"(lo), "=f"(hi) : "l"(v));
}
__device__ __forceinline__ void fma2(ull& d, ull a, ull b) {
    asm("fma.rn.f32x2 %0, %1, %2, %0;" : "+l"(d) : "l"(a), "l"(b));
}

// ---------------- K0: norm (blocks 0..1535) + weight prep (blocks 1536..1562) ----------------
__global__ void __launch_bounds__(192) k_norm_prep(
        const float* __restrict__ fl, const float* __restrict__ fr,
        const float* __restrict__ w_s, const float* __restrict__ w_m,
        const float* __restrict__ w_l, const float* __restrict__ w_pred1,
        const float* __restrict__ gamma, const float* __restrict__ beta,
        const float* __restrict__ mean, const float* __restrict__ var) {
    int blk = blockIdx.x;
    if (blk < 1536) {
        int idx = blk*192 + threadIdx.x;   // over BB*GG*HW exactly
        int pix = idx % HW;
        int bg  = idx / HW;
        const float* pl = fl + (size_t)bg*8*HW + pix;
        const float* pr = fr + (size_t)bg*8*HW + pix;
        float vl[8], vr[8];
        float sl = 0.f, sr = 0.f;
#pragma unroll
        for (int c = 0; c < 8; c++) {
            vl[c] = pl[c*HW]; sl += vl[c]*vl[c];
            vr[c] = pr[c*HW]; sr += vr[c]*vr[c];
        }
        float il = 1.0f / fmaxf(sqrtf(sl), 1e-12f);
        float ir = 1.0f / fmaxf(sqrtf(sr), 1e-12f);
        float* ol = g_fln + (size_t)idx*8;
        float* orr = g_frn + (size_t)idx*8;
#pragma unroll
        for (int c = 0; c < 8; c++) { ol[c] = vl[c]*il; orr[c] = vr[c]*ir; }
    } else {
        int tid = (blk - 1536)*192 + threadIdx.x;   // 0..5183
        // un-dup'd 3d conv weights: dst [s][kd][kh][gi][kw][g]
        {
            int i = tid;
            int g  = i & 7;
            int kw = (i >> 3) % 3;
            int gi = (i / 24) & 7;
            int kh = (i / 192) % 3;
            int kd = (i / 576) % 3;
            int s  = i / 1728;
            const float* w = (s == 0) ? w_s : ((s == 1) ? w_m : w_l);
            g_wpack2[i] = w[(g*8 + gi)*27 + (kd*3 + kh)*3 + kw];
        }
        // pred1 weights: src (oc, ic, kh, kw) -> dst [ic][t][oc]
        for (int i = tid; i < 65*9*32; i += 5184) {
            int oc = i & 31;
            int t  = (i >> 5) % 9;
            int ic = i / 288;
            g_w1pack[i] = w_pred1[(oc*65 + ic)*9 + t];
        }
        if (tid < 32) {
            float sc = gamma[tid] * rsqrtf(var[tid] + 1e-5f);
            g_bnscale[tid] = sc;
            g_bnbias[tid]  = beta[tid] - mean[tid]*sc;
        }
    }
}

// ---------------- K1: pred_part (blocks 0..767) + corr (blocks 768..2303) ----------------
__global__ void __launch_bounds__(192) k_corr_pred(const float* __restrict__ feat_l,
                                                   const float* __restrict__ edge) {
    __shared__ __align__(16) float sW[17*9*32];
    int blk = blockIdx.x;
    int tid = threadIdx.x;

    if (blk < BB*HH*NCH) {
        // ---- predictor conv partials ----
        int h = blk % HH;
        int t2 = blk / HH;
        int chunk = t2 % NCH;
        int b = t2 / NCH;
        int c0 = (chunk == 0) ? 0 : (17 + 16*(chunk - 1));
        int cn = (chunk == 0) ? 17 : 16;
        for (int i = tid; i < cn*288; i += 192) sW[i] = g_w1pack[c0*288 + i];
        __syncthreads();

        int w = tid;
        ull acc[16];
#pragma unroll
        for (int k = 0; k < 16; k++) acc[k] = 0ull;

        for (int ic2 = 0; ic2 < cn; ic2++) {
            int ic = c0 + ic2;
            const float* xin = (ic < 64) ? (feat_l + (size_t)(b*64 + ic)*HW)
                                         : (edge + (size_t)b*HW);
#pragma unroll
            for (int kh = 0; kh < 3; kh++) {
                int hh = h + kh - 1;
                if ((unsigned)hh >= HH) continue;
#pragma unroll
                for (int kw = 0; kw < 3; kw++) {
                    int ww = w + kw - 1;
                    if ((unsigned)ww >= WW) continue;
                    float xv = xin[hh*WW + ww];
                    ull xp = pk2(xv, xv);
                    const ulonglong2* wp = (const ulonglong2*)&sW[(ic2*9 + kh*3 + kw)*32];
#pragma unroll
                    for (int j = 0; j < 8; j++) {
                        ulonglong2 v = wp[j];
                        fma2(acc[2*j],   v.x, xp);
                        fma2(acc[2*j+1], v.y, xp);
                    }
                }
            }
        }
        float* op = g_pmid + (size_t)chunk*(BB*32*HW) + (size_t)(b*32)*HW + h*WW + w;
#pragma unroll
        for (int k = 0; k < 16; k++) {
            float lo, hi; upk2(lo, hi, acc[k]);
            op[(size_t)(2*k)*HW]   = lo;
            op[(size_t)(2*k+1)*HW] = hi;
        }
    } else {
        // ---- correlation volume ----
        int idx = (blk - BB*HH*NCH)*192 + tid;   // over BB*GG*HW exactly
        int w = idx % WW;
        int rest = idx / WW;
        int h = rest % HH;
        int bg = rest / HH;
        int g = bg & 7, b = bg >> 3;
        const float4* fl4 = (const float4*)(g_fln + (size_t)idx*8);
        float4 a0 = fl4[0], a1 = fl4[1];
        const float inv = 0.35355339059327373f;
        const float* frrow = g_frn + ((size_t)(bg*HH + h)*WW)*8;
        float* op = g_base + ((size_t)b*DD*GG + g)*HW + h*WW + w;
        for (int d = 0; d < DD; d++) {
            float val = 0.f;
            if (w >= d) {
                const float4* f4 = (const float4*)(frrow + (size_t)(w - d)*8);
                float4 b0 = f4[0], b1 = f4[1];
                val = (a0.x*b0.x + a0.y*b0.y + a0.z*b0.z + a0.w*b0.w +
                       a1.x*b1.x + a1.y*b1.y + a1.z*b1.z + a1.w*b1.w) * inv;
            }
            op[(size_t)d*GG*HW] = val;
        }
    }
}

// ---------------- K2: combine partials + BN + ReLU + 1x1 + softmax ----------------
__global__ void k_pred_fin(const float* __restrict__ w2, const float* __restrict__ b2,
                           const float* __restrict__ temp) {
    int idx = blockIdx.x * blockDim.x + threadIdx.x;
    if (idx >= BB*HW) return;
    int b = idx / HW;
    int pix = idx % HW;
    float l0 = b2[0], l1 = b2[1], l2 = b2[2];
    const float* base = g_pmid + (size_t)(b*32)*HW + pix;
#pragma unroll 4
    for (int o = 0; o < 32; o++) {
        float v = 0.f;
#pragma unroll
        for (int c = 0; c < NCH; c++)
            v += base[(size_t)c*(BB*32*HW) + (size_t)o*HW];
        v = fmaxf(v*g_bnscale[o] + g_bnbias[o], 0.f);
        l0 += __ldg(&w2[o])      * v;
        l1 += __ldg(&w2[32 + o]) * v;
        l2 += __ldg(&w2[64 + o]) * v;
    }
    float t = fmaxf(temp[0], 0.1f);
    l0 /= t; l1 /= t; l2 /= t;
    float m = fmaxf(l0, fmaxf(l1, l2));
    float e0 = expf(l0 - m), e1 = expf(l1 - m), e2 = expf(l2 - m);
    float r = 1.0f / (e0 + e1 + e2);
    g_sw2[0*BB*HW + idx] = e0*r;
    g_sw2[1*BB*HW + idx] = e1*r;
    g_sw2[2*BB*HW + idx] = e2*r;
}

// ---------------- K3: fused 3-scale dilated conv3d + blend + 1x1x1 ----------------
// 2px x d-PAIR, g-pair accumulator lanes, softmax blend folded into the data
// (x -> q_s*x), so NO per-scale acc registers. Weights loaded once per gi feed
// both d outputs: per gi 6 LDS.128 + 6 LDG serve 48 fma2.
__global__ void __launch_bounds__(192) k_fuse(const float* __restrict__ wf,
                                              const float* __restrict__ bfin,
                                              float* __restrict__ out) {
    __shared__ __align__(16) float sWt[5184];    // 20.7 KB un-dup weights
    __shared__ __align__(16) float sWf[256];
    __shared__ float sBf[32];
    int tid = threadIdx.x;
    for (int i = tid; i < 5184; i += 192) sWt[i] = g_wpack2[i];
    for (int i = tid; i < 256; i += 192) sWf[i] = wf[i];
    if (tid < 32) sBf[tid] = bfin[tid];
    __syncthreads();

    int lw = tid % 96;
    int dz = tid / 96;           // 0..1 (warp-uniform)
    int w0 = lw * 2;
    int h  = blockIdx.x % HH;
    int bd = blockIdx.x / HH;
    int d0 = (bd % 12)*4 + dz*2; // this thread: d0, d0+1
    int b  = bd / 12;

    int pix0 = h*WW + w0;

    // per-px softmax weights per scale
    float2 qs0 = *(const float2*)(g_sw2 + 0*BB*HW + (size_t)b*HW + pix0);
    float2 qs1 = *(const float2*)(g_sw2 + 1*BB*HW + (size_t)b*HW + pix0);
    float2 qs2 = *(const float2*)(g_sw2 + 2*BB*HW + (size_t)b*HW + pix0);

    ull fu[2][2][4];             // [d][px][gpair]
#pragma unroll
    for (int p = 0; p < 2; p++)
#pragma unroll
        for (int x = 0; x < 2; x++)
#pragma unroll
            for (int g = 0; g < 4; g++) fu[p][x][g] = 0ull;

    const float* bb = g_base + (size_t)b*DD*GG*HW;

#pragma unroll
    for (int s = 0; s < 3; s++) {
        const int dil = 1 << s;
        const int aoff = (s == 2) ? 4 : 2;
        bool aok = (w0 >= aoff);
        bool cok = (w0 + aoff + 1 < WW);
        float2 qs = (s == 0) ? qs0 : ((s == 1) ? qs1 : qs2);

#pragma unroll 1
        for (int kd = 0; kd < 3; kd++) {
            int dda = d0 + (kd - 1)*dil;
            bool va = (unsigned)dda < DD;
            bool vb = (unsigned)(dda + 1) < DD;
            if (!(va | vb)) continue;
#pragma unroll 1
            for (int kh = 0; kh < 3; kh++) {
                int hh = h + (kh - 1)*dil;
                if ((unsigned)hh >= HH) continue;
                const float* rowa = bb + (size_t)dda*GG*HW + hh*WW;
                const float* swrow = &sWt[((s*3 + kd)*3 + kh)*192];
#pragma unroll
                for (int gi = 0; gi < 8; gi++) {
                    const float* pa = rowa + gi*HW;        // tap row for d0
                    const float* pb = pa + GG*HW;          // tap row for d0+1
                    // raw tap values x[kw][px] for both d
                    float xa[3][2], xb[3][2];
                    if (s == 0) {
                        float2 Ba = va ? *(const float2*)(pa + w0) : make_float2(0.f, 0.f);
                        float ava = (va & aok) ? pa[w0 - 1] : 0.f;
                        float cva = (va & cok) ? pa[w0 + 2] : 0.f;
                        xa[0][0] = ava;  xa[0][1] = Ba.x;
                        xa[1][0] = Ba.x; xa[1][1] = Ba.y;
                        xa[2][0] = Ba.y; xa[2][1] = cva;
                        float2 Bb = vb ? *(const float2*)(pb + w0) : make_float2(0.f, 0.f);
                        float avb = (vb & aok) ? pb[w0 - 1] : 0.f;
                        float cvb = (vb & cok) ? pb[w0 + 2] : 0.f;
                        xb[0][0] = avb;  xb[0][1] = Bb.x;
                        xb[1][0] = Bb.x; xb[1][1] = Bb.y;
                        xb[2][0] = Bb.y; xb[2][1] = cvb;
                    } else {
                        float2 Aa = (va & aok) ? *(const float2*)(pa + w0 - aoff) : make_float2(0.f, 0.f);
                        float2 Ba = va ? *(const float2*)(pa + w0) : make_float2(0.f, 0.f);
                        float2 Ca = (va & cok) ? *(const float2*)(pa + w0 + aoff) : make_float2(0.f, 0.f);
                        xa[0][0] = Aa.x; xa[0][1] = Aa.y;
                        xa[1][0] = Ba.x; xa[1][1] = Ba.y;
                        xa[2][0] = Ca.x; xa[2][1] = Ca.y;
                        float2 Ab = (vb & aok) ? *(const float2*)(pb + w0 - aoff) : make_float2(0.f, 0.f);
                        float2 Bb = vb ? *(const float2*)(pb + w0) : make_float2(0.f, 0.f);
                        float2 Cb = (vb & cok) ? *(const float2*)(pb + w0 + aoff) : make_float2(0.f, 0.f);
                        xb[0][0] = Ab.x; xb[0][1] = Ab.y;
                        xb[1][0] = Bb.x; xb[1][1] = Bb.y;
                        xb[2][0] = Cb.x; xb[2][1] = Cb.y;
                    }
                    const ulonglong2* wk = (const ulonglong2*)(swrow + gi*24);
#pragma unroll
                    for (int kw = 0; kw < 3; kw++) {
                        ulonglong2 wv0 = wk[2*kw], wv1 = wk[2*kw + 1];
                        float t; ull m;
                        t = xa[kw][0]*qs.x; m = pk2(t, t);
                        fma2(fu[0][0][0], wv0.x, m); fma2(fu[0][0][1], wv0.y, m);
                        fma2(fu[0][0][2], wv1.x, m); fma2(fu[0][0][3], wv1.y, m);
                        t = xa[kw][1]*qs.y; m = pk2(t, t);
                        fma2(fu[0][1][0], wv0.x, m); fma2(fu[0][1][1], wv0.y, m);
                        fma2(fu[0][1][2], wv1.x, m); fma2(fu[0][1][3], wv1.y, m);
                        t = xb[kw][0]*qs.x; m = pk2(t, t);
                        fma2(fu[1][0][0], wv0.x, m); fma2(fu[1][0][1], wv0.y, m);
                        fma2(fu[1][0][2], wv1.x, m); fma2(fu[1][0][3], wv1.y, m);
                        t = xb[kw][1]*qs.y; m = pk2(t, t);
                        fma2(fu[1][1][0], wv0.x, m); fma2(fu[1][1][1], wv0.y, m);
                        fma2(fu[1][1][2], wv1.x, m); fma2(fu[1][1][3], wv1.y, m);
                    }
                }
            }
        }
    }

    // epilogue: 1x1x1 conv to 32 channels for both d (un-dup weights, hadd)
#pragma unroll
    for (int pd = 0; pd < 2; pd++) {
        float* op = out + (((size_t)b*32)*DD + (d0 + pd))*HW + pix0;
#pragma unroll
        for (int o = 0; o < 32; o++) {
            const ulonglong2* wo = (const ulonglong2*)&sWf[o*8];
            ulonglong2 wv0 = wo[0], wv1 = wo[1];
            ull a0 = 0ull, a1 = 0ull;
            fma2(a0, wv0.x, fu[pd][0][0]); fma2(a1, wv0.x, fu[pd][1][0]);
            fma2(a0, wv0.y, fu[pd][0][1]); fma2(a1, wv0.y, fu[pd][1][1]);
            fma2(a0, wv1.x, fu[pd][0][2]); fma2(a1, wv1.x, fu[pd][1][2]);
            fma2(a0, wv1.y, fu[pd][0][3]); fma2(a1, wv1.y, fu[pd][1][3]);
            float e0, e1, f0, f1;
            upk2(e0, e1, a0);
            upk2(f0, f1, a1);
            float bias = sBf[o];
            __stcs((float2*)(op + (size_t)o*DD*HW),
                   make_float2(bias + e0 + e1, bias + f0 + f1));
        }
    }
}

// ---------------- launch ----------------
extern "C" void kernel_launch(void* const* d_in, const int* in_sizes, int n_in,
                              void* d_out, int out_size) {
    const float* feat_l  = (const float*)d_in[0];
    const float* feat_r  = (const float*)d_in[1];
    const float* edge    = (const float*)d_in[2];
    const float* w_pred1 = (const float*)d_in[3];
    const float* gamma   = (const float*)d_in[4];
    const float* beta    = (const float*)d_in[5];
    const float* mean    = (const float*)d_in[6];
    const float* var     = (const float*)d_in[7];
    const float* w_pred2 = (const float*)d_in[8];
    const float* b_pred2 = (const float*)d_in[9];
    const float* temp    = (const float*)d_in[10];
    const float* w_s     = (const float*)d_in[11];
    const float* w_m     = (const float*)d_in[12];
    const float* w_l     = (const float*)d_in[13];
    const float* w_final = (const float*)d_in[14];
    const float* b_final = (const float*)d_in[15];
    float* out = (float*)d_out;

    // launch idx 0: norm + weight prep
    k_norm_prep<<<1536 + 27, 192>>>(feat_l, feat_r, w_s, w_m, w_l, w_pred1,
                                    gamma, beta, mean, var);
    // launch idx 1: pred_part + corr
    k_corr_pred<<<BB*HH*NCH + 1536, 192>>>(feat_l, edge);
    // launch idx 2: softmax weights
    k_pred_fin<<<(BB*HW + 255)/256, 256>>>(w_pred2, b_pred2, temp);
    // launch idx 3: the big one (ncu capture lands here)
    k_fuse<<<BB*12*HH, 192>>>(w_final, b_final, out);
}

// round 17
// speedup vs baseline: 1.1644x; 1.1644x over previous
#include <cuda_runtime.h>

#define BB 2
#define CC 64
#define HH 96
#define WW 192
#define DD 48
#define GG 8
#define HW (HH*WW)
#define NCH 4

// ---------------- scratch (static device globals; no allocation) ----------------
__device__ float g_fln[BB*GG*HW*8];              // [b][g][h][w][c]
__device__ float g_frn[BB*GG*HW*8];              // [b][g][h][w][c]
__device__ float g_base[(size_t)BB*DD*GG*HW];    // [b][d][g][h][w]
__device__ float g_sw2[3*BB*HW];                 // [s][b][hw]
__device__ float g_wpack2[5184];                 // [s][kd][kh][gi][kw][g] (un-dup)
__device__ float g_w1pack[65*9*32];              // [ic][tap][oc]
__device__ float g_pmid[(size_t)NCH*BB*32*HW];   // partial conv32 outputs
__device__ float g_bnscale[32];
__device__ float g_bnbias[32];

// ---------------- f32x2 helpers ----------------
typedef unsigned long long ull;
__device__ __forceinline__ ull pk2(float lo, float hi) {
    ull r;
    asm("mov.b64 %0, {%1, %2};" : "=l"(r) : "f"(lo), "f"(hi));
    return r;
}
__device__ __forceinline__ void upk2(float& lo, float& hi, ull v) {
    asm("mov.b64 {%0, %1}, %2;" : "=f"(lo), "=f"(hi) : "l"(v));
}
__device__ __forceinline__ void fma2(ull& d, ull a, ull b) {
    asm("fma.rn.f32x2 %0, %1, %2, %0;" : "+l"(d) : "l"(a), "l"(b));
}

// ---------------- K0: norm (blocks 0..1535) + weight prep (blocks 1536..1562) ----------------
__global__ void __launch_bounds__(192) k_norm_prep(
        const float* __restrict__ fl, const float* __restrict__ fr,
        const float* __restrict__ w_s, const float* __restrict__ w_m,
        const float* __restrict__ w_l, const float* __restrict__ w_pred1,
        const float* __restrict__ gamma, const float* __restrict__ beta,
        const float* __restrict__ mean, const float* __restrict__ var) {
    int blk = blockIdx.x;
    if (blk < 1536) {
        int idx = blk*192 + threadIdx.x;   // over BB*GG*HW exactly
        int pix = idx % HW;
        int bg  = idx / HW;
        const float* pl = fl + (size_t)bg*8*HW + pix;
        const float* pr = fr + (size_t)bg*8*HW + pix;
        float vl[8], vr[8];
        float sl = 0.f, sr = 0.f;
#pragma unroll
        for (int c = 0; c < 8; c++) {
            vl[c] = pl[c*HW]; sl += vl[c]*vl[c];
            vr[c] = pr[c*HW]; sr += vr[c]*vr[c];
        }
        float il = 1.0f / fmaxf(sqrtf(sl), 1e-12f);
        float ir = 1.0f / fmaxf(sqrtf(sr), 1e-12f);
        float* ol = g_fln + (size_t)idx*8;
        float* orr = g_frn + (size_t)idx*8;
#pragma unroll
        for (int c = 0; c < 8; c++) { ol[c] = vl[c]*il; orr[c] = vr[c]*ir; }
    } else {
        int tid = (blk - 1536)*192 + threadIdx.x;   // 0..5183
        // un-dup'd 3d conv weights: dst [s][kd][kh][gi][kw][g]
        {
            int i = tid;
            int g  = i & 7;
            int kw = (i >> 3) % 3;
            int gi = (i / 24) & 7;
            int kh = (i / 192) % 3;
            int kd = (i / 576) % 3;
            int s  = i / 1728;
            const float* w = (s == 0) ? w_s : ((s == 1) ? w_m : w_l);
            g_wpack2[i] = w[(g*8 + gi)*27 + (kd*3 + kh)*3 + kw];
        }
        // pred1 weights: src (oc, ic, kh, kw) -> dst [ic][t][oc]
        for (int i = tid; i < 65*9*32; i += 5184) {
            int oc = i & 31;
            int t  = (i >> 5) % 9;
            int ic = i / 288;
            g_w1pack[i] = w_pred1[(oc*65 + ic)*9 + t];
        }
        if (tid < 32) {
            float sc = gamma[tid] * rsqrtf(var[tid] + 1e-5f);
            g_bnscale[tid] = sc;
            g_bnbias[tid]  = beta[tid] - mean[tid]*sc;
        }
    }
}

// ---------------- K1: pred_part (blocks 0..767) + corr (blocks 768..2303) ----------------
__global__ void __launch_bounds__(192) k_corr_pred(const float* __restrict__ feat_l,
                                                   const float* __restrict__ edge) {
    __shared__ __align__(16) float sW[17*9*32];
    int blk = blockIdx.x;
    int tid = threadIdx.x;

    if (blk < BB*HH*NCH) {
        // ---- predictor conv partials ----
        int h = blk % HH;
        int t2 = blk / HH;
        int chunk = t2 % NCH;
        int b = t2 / NCH;
        int c0 = (chunk == 0) ? 0 : (17 + 16*(chunk - 1));
        int cn = (chunk == 0) ? 17 : 16;
        for (int i = tid; i < cn*288; i += 192) sW[i] = g_w1pack[c0*288 + i];
        __syncthreads();

        int w = tid;
        ull acc[16];
#pragma unroll
        for (int k = 0; k < 16; k++) acc[k] = 0ull;

        for (int ic2 = 0; ic2 < cn; ic2++) {
            int ic = c0 + ic2;
            const float* xin = (ic < 64) ? (feat_l + (size_t)(b*64 + ic)*HW)
                                         : (edge + (size_t)b*HW);
#pragma unroll
            for (int kh = 0; kh < 3; kh++) {
                int hh = h + kh - 1;
                if ((unsigned)hh >= HH) continue;
#pragma unroll
                for (int kw = 0; kw < 3; kw++) {
                    int ww = w + kw - 1;
                    if ((unsigned)ww >= WW) continue;
                    float xv = xin[hh*WW + ww];
                    ull xp = pk2(xv, xv);
                    const ulonglong2* wp = (const ulonglong2*)&sW[(ic2*9 + kh*3 + kw)*32];
#pragma unroll
                    for (int j = 0; j < 8; j++) {
                        ulonglong2 v = wp[j];
                        fma2(acc[2*j],   v.x, xp);
                        fma2(acc[2*j+1], v.y, xp);
                    }
                }
            }
        }
        float* op = g_pmid + (size_t)chunk*(BB*32*HW) + (size_t)(b*32)*HW + h*WW + w;
#pragma unroll
        for (int k = 0; k < 16; k++) {
            float lo, hi; upk2(lo, hi, acc[k]);
            __stcs(op + (size_t)(2*k)*HW,   lo);
            __stcs(op + (size_t)(2*k+1)*HW, hi);
        }
    } else {
        // ---- correlation volume ----
        int idx = (blk - BB*HH*NCH)*192 + tid;   // over BB*GG*HW exactly
        int w = idx % WW;
        int rest = idx / WW;
        int h = rest % HH;
        int bg = rest / HH;
        int g = bg & 7, b = bg >> 3;
        const float4* fl4 = (const float4*)(g_fln + (size_t)idx*8);
        float4 a0 = fl4[0], a1 = fl4[1];
        const float inv = 0.35355339059327373f;
        const float* frrow = g_frn + ((size_t)(bg*HH + h)*WW)*8;
        float* op = g_base + ((size_t)b*DD*GG + g)*HW + h*WW + w;
        for (int d = 0; d < DD; d++) {
            float val = 0.f;
            if (w >= d) {
                const float4* f4 = (const float4*)(frrow + (size_t)(w - d)*8);
                float4 b0 = f4[0], b1 = f4[1];
                val = (a0.x*b0.x + a0.y*b0.y + a0.z*b0.z + a0.w*b0.w +
                       a1.x*b1.x + a1.y*b1.y + a1.z*b1.z + a1.w*b1.w) * inv;
            }
            op[(size_t)d*GG*HW] = val;
        }
    }
}

// ---------------- K2: combine partials + BN + ReLU + 1x1 + softmax ----------------
__global__ void k_pred_fin(const float* __restrict__ w2, const float* __restrict__ b2,
                           const float* __restrict__ temp) {
    int idx = blockIdx.x * blockDim.x + threadIdx.x;
    if (idx >= BB*HW) return;
    int b = idx / HW;
    int pix = idx % HW;
    float l0 = b2[0], l1 = b2[1], l2 = b2[2];
    const float* base = g_pmid + (size_t)(b*32)*HW + pix;
#pragma unroll 4
    for (int o = 0; o < 32; o++) {
        float v = 0.f;
#pragma unroll
        for (int c = 0; c < NCH; c++)
            v += base[(size_t)c*(BB*32*HW) + (size_t)o*HW];
        v = fmaxf(v*g_bnscale[o] + g_bnbias[o], 0.f);
        l0 += __ldg(&w2[o])      * v;
        l1 += __ldg(&w2[32 + o]) * v;
        l2 += __ldg(&w2[64 + o]) * v;
    }
    float t = fmaxf(temp[0], 0.1f);
    l0 /= t; l1 /= t; l2 /= t;
    float m = fmaxf(l0, fmaxf(l1, l2));
    float e0 = expf(l0 - m), e1 = expf(l1 - m), e2 = expf(l2 - m);
    float r = 1.0f / (e0 + e1 + e2);
    g_sw2[0*BB*HW + idx] = e0*r;
    g_sw2[1*BB*HW + idx] = e1*r;
    g_sw2[2*BB*HW + idx] = e2*r;
}

// ---------------- K3: fused 3-scale dilated conv3d + blend + 1x1x1 ----------------
// d-PAIR, g-pair lanes, blend folded into data (x -> q*x), gi loop NOT unrolled
// to contain register pressure. Per gi: 6 LDS.128 + 6 LDG serve 2 d outputs
// (weight wavefronts amortized over 2 d: -35% L1 wf vs R14).
__global__ void __launch_bounds__(192) k_fuse(const float* __restrict__ wf,
                                              const float* __restrict__ bfin,
                                              float* __restrict__ out) {
    __shared__ __align__(16) float sWt[5184];    // 20.7 KB un-dup weights
    __shared__ __align__(16) float sWf[256];
    __shared__ float sBf[32];
    int tid = threadIdx.x;
    for (int i = tid; i < 5184; i += 192) sWt[i] = g_wpack2[i];
    for (int i = tid; i < 256; i += 192) sWf[i] = wf[i];
    if (tid < 32) sBf[tid] = bfin[tid];
    __syncthreads();

    int lw = tid % 96;
    int dz = tid / 96;           // 0..1 (warp-uniform)
    int w0 = lw * 2;
    int h  = blockIdx.x % HH;
    int bd = blockIdx.x / HH;
    int d0 = (bd % 12)*4 + dz*2; // this thread: d0, d0+1
    int b  = bd / 12;

    int pix0 = h*WW + w0;

    ull fu[2][2][4];             // [d][px][gpair]
#pragma unroll
    for (int p = 0; p < 2; p++)
#pragma unroll
        for (int x = 0; x < 2; x++)
#pragma unroll
            for (int g = 0; g < 4; g++) fu[p][x][g] = 0ull;

    const float* bb = g_base + (size_t)b*DD*GG*HW;

#pragma unroll
    for (int s = 0; s < 3; s++) {
        const int dil = 1 << s;
        const int aoff = (s == 2) ? 4 : 2;
        bool aok = (w0 >= aoff);
        bool cok = (w0 + aoff + 1 < WW);
        float2 qs = *(const float2*)(g_sw2 + (size_t)s*BB*HW + (size_t)b*HW + pix0);

#pragma unroll 1
        for (int kd = 0; kd < 3; kd++) {
            int dda = d0 + (kd - 1)*dil;
            bool va = (unsigned)dda < DD;
            bool vb = (unsigned)(dda + 1) < DD;
            if (!(va | vb)) continue;
#pragma unroll 1
            for (int kh = 0; kh < 3; kh++) {
                int hh = h + (kh - 1)*dil;
                if ((unsigned)hh >= HH) continue;
                const float* rowa = bb + (size_t)dda*GG*HW + hh*WW;
                const float* swrow = &sWt[((s*3 + kd)*3 + kh)*192];
#pragma unroll 1
                for (int gi = 0; gi < 8; gi++) {
                    const float* pa = rowa + gi*HW;        // tap row for d0
                    const float* pb = pa + GG*HW;          // tap row for d0+1
                    // load + pre-scale taps (6 values per d)
                    float a0v, a1v, b0v, b1v, c0v, c1v;    // d0
                    float a2v, a3v, b2v, b3v, c2v, c3v;    // d0+1
                    if (s == 0) {
                        float2 Ba = va ? *(const float2*)(pa + w0) : make_float2(0.f, 0.f);
                        b0v = Ba.x; b1v = Ba.y;
                        a0v = (va & aok) ? pa[w0 - 1] : 0.f;
                        a1v = b0v;
                        c0v = b1v;
                        c1v = (va & cok) ? pa[w0 + 2] : 0.f;
                        float2 Bb = vb ? *(const float2*)(pb + w0) : make_float2(0.f, 0.f);
                        b2v = Bb.x; b3v = Bb.y;
                        a2v = (vb & aok) ? pb[w0 - 1] : 0.f;
                        a3v = b2v;
                        c2v = b3v;
                        c3v = (vb & cok) ? pb[w0 + 2] : 0.f;
                    } else {
                        float2 Aa = (va & aok) ? *(const float2*)(pa + w0 - aoff) : make_float2(0.f, 0.f);
                        float2 Ba = va ? *(const float2*)(pa + w0) : make_float2(0.f, 0.f);
                        float2 Ca = (va & cok) ? *(const float2*)(pa + w0 + aoff) : make_float2(0.f, 0.f);
                        a0v = Aa.x; a1v = Aa.y; b0v = Ba.x; b1v = Ba.y; c0v = Ca.x; c1v = Ca.y;
                        float2 Ab = (vb & aok) ? *(const float2*)(pb + w0 - aoff) : make_float2(0.f, 0.f);
                        float2 Bb = vb ? *(const float2*)(pb + w0) : make_float2(0.f, 0.f);
                        float2 Cb = (vb & cok) ? *(const float2*)(pb + w0 + aoff) : make_float2(0.f, 0.f);
                        a2v = Ab.x; a3v = Ab.y; b2v = Bb.x; b3v = Bb.y; c2v = Cb.x; c3v = Cb.y;
                    }
                    const ulonglong2* wk = (const ulonglong2*)(swrow + gi*24);
                    ulonglong2 wk0 = wk[0], wk1 = wk[1];   // kw=0
                    ulonglong2 wk2 = wk[2], wk3 = wk[3];   // kw=1
                    ulonglong2 wk4 = wk[4], wk5 = wk[5];   // kw=2
                    float t; ull m;
                    // kw=0: tap A, px0 scale q.x / px1 scale q.y
                    t = a0v*qs.x; m = pk2(t, t);
                    fma2(fu[0][0][0], wk0.x, m); fma2(fu[0][0][1], wk0.y, m);
                    fma2(fu[0][0][2], wk1.x, m); fma2(fu[0][0][3], wk1.y, m);
                    t = a1v*qs.y; m = pk2(t, t);
                    fma2(fu[0][1][0], wk0.x, m); fma2(fu[0][1][1], wk0.y, m);
                    fma2(fu[0][1][2], wk1.x, m); fma2(fu[0][1][3], wk1.y, m);
                    t = a2v*qs.x; m = pk2(t, t);
                    fma2(fu[1][0][0], wk0.x, m); fma2(fu[1][0][1], wk0.y, m);
                    fma2(fu[1][0][2], wk1.x, m); fma2(fu[1][0][3], wk1.y, m);
                    t = a3v*qs.y; m = pk2(t, t);
                    fma2(fu[1][1][0], wk0.x, m); fma2(fu[1][1][1], wk0.y, m);
                    fma2(fu[1][1][2], wk1.x, m); fma2(fu[1][1][3], wk1.y, m);
                    // kw=1: tap B
                    t = b0v*qs.x; m = pk2(t, t);
                    fma2(fu[0][0][0], wk2.x, m); fma2(fu[0][0][1], wk2.y, m);
                    fma2(fu[0][0][2], wk3.x, m); fma2(fu[0][0][3], wk3.y, m);
                    t = b1v*qs.y; m = pk2(t, t);
                    fma2(fu[0][1][0], wk2.x, m); fma2(fu[0][1][1], wk2.y, m);
                    fma2(fu[0][1][2], wk3.x, m); fma2(fu[0][1][3], wk3.y, m);
                    t = b2v*qs.x; m = pk2(t, t);
                    fma2(fu[1][0][0], wk2.x, m); fma2(fu[1][0][1], wk2.y, m);
                    fma2(fu[1][0][2], wk3.x, m); fma2(fu[1][0][3], wk3.y, m);
                    t = b3v*qs.y; m = pk2(t, t);
                    fma2(fu[1][1][0], wk2.x, m); fma2(fu[1][1][1], wk2.y, m);
                    fma2(fu[1][1][2], wk3.x, m); fma2(fu[1][1][3], wk3.y, m);
                    // kw=2: tap C
                    t = c0v*qs.x; m = pk2(t, t);
                    fma2(fu[0][0][0], wk4.x, m); fma2(fu[0][0][1], wk4.y, m);
                    fma2(fu[0][0][2], wk5.x, m); fma2(fu[0][0][3], wk5.y, m);
                    t = c1v*qs.y; m = pk2(t, t);
                    fma2(fu[0][1][0], wk4.x, m); fma2(fu[0][1][1], wk4.y, m);
                    fma2(fu[0][1][2], wk5.x, m); fma2(fu[0][1][3], wk5.y, m);
                    t = c2v*qs.x; m = pk2(t, t);
                    fma2(fu[1][0][0], wk4.x, m); fma2(fu[1][0][1], wk4.y, m);
                    fma2(fu[1][0][2], wk5.x, m); fma2(fu[1][0][3], wk5.y, m);
                    t = c3v*qs.y; m = pk2(t, t);
                    fma2(fu[1][1][0], wk4.x, m); fma2(fu[1][1][1], wk4.y, m);
                    fma2(fu[1][1][2], wk5.x, m); fma2(fu[1][1][3], wk5.y, m);
                }
            }
        }
    }

    // epilogue: 1x1x1 conv to 32 channels for both d (un-dup weights, hadd)
#pragma unroll 1
    for (int pd = 0; pd < 2; pd++) {
        float* op = out + (((size_t)b*32)*DD + (d0 + pd))*HW + pix0;
#pragma unroll
        for (int o = 0; o < 32; o++) {
            const ulonglong2* wo = (const ulonglong2*)&sWf[o*8];
            ulonglong2 wv0 = wo[0], wv1 = wo[1];
            ull a0 = 0ull, a1 = 0ull;
            fma2(a0, wv0.x, fu[pd][0][0]); fma2(a1, wv0.x, fu[pd][1][0]);
            fma2(a0, wv0.y, fu[pd][0][1]); fma2(a1, wv0.y, fu[pd][1][1]);
            fma2(a0, wv1.x, fu[pd][0][2]); fma2(a1, wv1.x, fu[pd][1][2]);
            fma2(a0, wv1.y, fu[pd][0][3]); fma2(a1, wv1.y, fu[pd][1][3]);
            float e0, e1, f0, f1;
            upk2(e0, e1, a0);
            upk2(f0, f1, a1);
            float bias = sBf[o];
            __stcs((float2*)(op + (size_t)o*DD*HW),
                   make_float2(bias + e0 + e1, bias + f0 + f1));
        }
    }
}

// ---------------- launch ----------------
extern "C" void kernel_launch(void* const* d_in, const int* in_sizes, int n_in,
                              void* d_out, int out_size) {
    const float* feat_l  = (const float*)d_in[0];
    const float* feat_r  = (const float*)d_in[1];
    const float* edge    = (const float*)d_in[2];
    const float* w_pred1 = (const float*)d_in[3];
    const float* gamma   = (const float*)d_in[4];
    const float* beta    = (const float*)d_in[5];
    const float* mean    = (const float*)d_in[6];
    const float* var     = (const float*)d_in[7];
    const float* w_pred2 = (const float*)d_in[8];
    const float* b_pred2 = (const float*)d_in[9];
    const float* temp    = (const float*)d_in[10];
    const float* w_s     = (const float*)d_in[11];
    const float* w_m     = (const float*)d_in[12];
    const float* w_l     = (const float*)d_in[13];
    const float* w_final = (const float*)d_in[14];
    const float* b_final = (const float*)d_in[15];
    float* out = (float*)d_out;

    // launch idx 0: norm + weight prep
    k_norm_prep<<<1536 + 27, 192>>>(feat_l, feat_r, w_s, w_m, w_l, w_pred1,
                                    gamma, beta, mean, var);
    // launch idx 1: pred_part + corr
    k_corr_pred<<<BB*HH*NCH + 1536, 192>>>(feat_l, edge);
    // launch idx 2: softmax weights
    k_pred_fin<<<(BB*HW + 255)/256, 256>>>(w_pred2, b_pred2, temp);
    // launch idx 3: the big one (ncu capture lands here)
    k_fuse<<<BB*12*HH, 192>>>(w_final, b_final, out);
}